// round 10
// baseline (speedup 1.0000x reference)
#include <cuda_runtime.h>
#include <cuda_bf16.h>

#define QT     577
#define NTOK   55392                  // 96 * 577 rows
#define MASK_ELEMS (96 * 577 * 577)
#define SIGMA_ELEMS (NTOK * 4)

// Fallback Sigma target if out buffer doesn't include Sigma
__device__ float g_sigma_fallback[SIGMA_ELEMS];

// ---------------------------------------------------------------------------
// Fused kernel: ONE WARP = ONE qidx x FOUR bh ROWS (bh strided by 2 so all
// four toks share parity -> identical float2 alignment AND identical (dy,dx)
// geometry). Per pair-iteration the walker + wrap-selects + geometric
// products A=dy^2, B=dy*dx, C=dx^2 are computed ONCE and reused by 4 rows;
// per-row quad = mul+2fma with the -0.5*log2(e) constant pre-folded into the
// coefficients (fmax(quad,0) becomes fmin(t2,0)).
// T==1 closed form expanded: m = pu / (1 - u - p + 2pu).
// max_k kernel == 1 exactly (PD form, zero CLS/self distance) => no row
// reduction needed.
// ---------------------------------------------------------------------------
__global__ __launch_bounds__(256, 4)
void mgk_fused(const float* __restrict__ q,
               const float* __restrict__ W1, const float* __restrict__ b1,
               const float* __restrict__ W2, const float* __restrict__ b2,
               const float* __restrict__ u,  const float* __restrict__ temp,
               float* __restrict__ mask, float* __restrict__ sigma)
{
    __shared__ float w1t[64 * 68];    // W1 transposed: w1t[j*68+k] = W1[k][j]
    __shared__ float qs[8][4][68];    // per-warp 4 q rows (float4-aligned)

    const int tid  = threadIdx.x;
    const int wid  = tid >> 5;
    const int lane = tid & 31;

    // ---- stage W1 transposed (once per block) ----
    for (int i = tid; i < 4096; i += 256) {
        const int k = i >> 6, j = i & 63;
        w1t[j * 68 + k] = W1[i];
    }

    const int j0 = lane, j1 = lane + 32;
    const float bb0 = b1[j0], bb1 = b1[j1];
    const float w2a0 = W2[j0 * 3 + 0], w2b0 = W2[j0 * 3 + 1], w2c0 = W2[j0 * 3 + 2];
    const float w2a1 = W2[j1 * 3 + 0], w2b1 = W2[j1 * 3 + 1], w2c1 = W2[j1 * 3 + 2];
    const float b20 = b2[0], b21 = b2[1], b22 = b2[2];
    const float T    = temp[0];
    const bool  isT1 = (T == 1.0f);
    const float invT = 1.0f / T;

    // ---- warp -> (qidx, 4 bh rows strided by 2, same parity) ----
    const int wg   = blockIdx.x * 8 + wid;     // 0..13847
    const int qidx = wg % 577;
    const int s    = wg / 577;                 // 0..23
    const int bh0  = (s >> 1) * 8 + (s & 1);   // {0,1,8,9,16,17,...}
    int tk[4];
#pragma unroll
    for (int r = 0; r < 4; r++) tk[r] = (bh0 + 2 * r) * QT + qidx;

    // ---- stage the warp's 4 q rows ----
#pragma unroll
    for (int r = 0; r < 4; r++) {
        qs[wid][r][lane]      = q[(size_t)tk[r] * 64 + lane];
        qs[wid][r][lane + 32] = q[(size_t)tk[r] * 64 + 32 + lane];
    }
    __syncthreads();

    // ---- layer 1: 4 rows x 2 units; w-loads amortized across rows ----
    float a00r = bb0, a01r = bb0, a02r = bb0, a03r = bb0;
    float a10r = bb1, a11r = bb1, a12r = bb1, a13r = bb1;
#pragma unroll
    for (int kk = 0; kk < 16; kk++) {
        const float4 wa = *(const float4*)&w1t[j0 * 68 + 4 * kk];
        const float4 wb = *(const float4*)&w1t[j1 * 68 + 4 * kk];
        const float4 q0 = *(const float4*)&qs[wid][0][4 * kk];
        const float4 q1 = *(const float4*)&qs[wid][1][4 * kk];
        const float4 q2 = *(const float4*)&qs[wid][2][4 * kk];
        const float4 q3 = *(const float4*)&qs[wid][3][4 * kk];
        a00r = fmaf(q0.x, wa.x, a00r); a00r = fmaf(q0.y, wa.y, a00r);
        a00r = fmaf(q0.z, wa.z, a00r); a00r = fmaf(q0.w, wa.w, a00r);
        a01r = fmaf(q1.x, wa.x, a01r); a01r = fmaf(q1.y, wa.y, a01r);
        a01r = fmaf(q1.z, wa.z, a01r); a01r = fmaf(q1.w, wa.w, a01r);
        a02r = fmaf(q2.x, wa.x, a02r); a02r = fmaf(q2.y, wa.y, a02r);
        a02r = fmaf(q2.z, wa.z, a02r); a02r = fmaf(q2.w, wa.w, a02r);
        a03r = fmaf(q3.x, wa.x, a03r); a03r = fmaf(q3.y, wa.y, a03r);
        a03r = fmaf(q3.z, wa.z, a03r); a03r = fmaf(q3.w, wa.w, a03r);
        a10r = fmaf(q0.x, wb.x, a10r); a10r = fmaf(q0.y, wb.y, a10r);
        a10r = fmaf(q0.z, wb.z, a10r); a10r = fmaf(q0.w, wb.w, a10r);
        a11r = fmaf(q1.x, wb.x, a11r); a11r = fmaf(q1.y, wb.y, a11r);
        a11r = fmaf(q1.z, wb.z, a11r); a11r = fmaf(q1.w, wb.w, a11r);
        a12r = fmaf(q2.x, wb.x, a12r); a12r = fmaf(q2.y, wb.y, a12r);
        a12r = fmaf(q2.z, wb.z, a12r); a12r = fmaf(q2.w, wb.w, a12r);
        a13r = fmaf(q3.x, wb.x, a13r); a13r = fmaf(q3.y, wb.y, a13r);
        a13r = fmaf(q3.z, wb.z, a13r); a13r = fmaf(q3.w, wb.w, a13r);
    }

    // ---- per-row: GELU, reduce, tail -> pre-scaled inverse coefs ----
    const float K2 = -0.72134752044448170f;    // -0.5*log2(e)
    float ca[4], cb[4], cd[4];
#pragma unroll
    for (int r4 = 0; r4 < 4; r4++) {
        const float h0 = (r4 == 0) ? a00r : (r4 == 1) ? a01r
                        : (r4 == 2) ? a02r : a03r;
        const float h1 = (r4 == 0) ? a10r : (r4 == 1) ? a11r
                        : (r4 == 2) ? a12r : a13r;

        // Exact GELU (erf-based, matches approximate=False)
        const float g0 = 0.5f * h0 * (1.0f + erff(h0 * 0.70710678118654752f));
        const float g1 = 0.5f * h1 * (1.0f + erff(h1 * 0.70710678118654752f));

        float p0 = fmaf(g1, w2a1, g0 * w2a0);
        float p1 = fmaf(g1, w2b1, g0 * w2b0);
        float p2 = fmaf(g1, w2c1, g0 * w2c0);
#pragma unroll
        for (int off = 16; off > 0; off >>= 1) {
            p0 += __shfl_xor_sync(0xffffffffu, p0, off);
            p1 += __shfl_xor_sync(0xffffffffu, p1, off);
            p2 += __shfl_xor_sync(0xffffffffu, p2, off);
        }

        const float s0 = p0 + b20, s1 = p1 + b21, s2 = p2 + b22;
        const float sy  = expf(s0) + 1.0f;
        const float sx  = expf(s1) + 1.0f;
        const float rho = tanhf(s2) * 0.99f;
        const float cov = sy * sx * rho;
        if (lane == 0)
            ((float4*)sigma)[tk[r4]] = make_float4(sy * sy, cov, cov, sx * sx);

        const float om = 1.0f - rho * rho;
        ca[r4] = K2 / (sy * sy * om);                 // scaled c00
        cb[r4] = K2 * (-2.0f * rho) / (sy * sx * om); // scaled 2*c01
        cd[r4] = K2 / (sx * sx * om);                 // scaled c11
    }

    // ---- mask rows ----
    if (qidx == 0) {
        // CLS query rows: probs=1 -> mask=1 for ANY T.
#pragma unroll
        for (int r = 0; r < 4; r++) {
            float* mrow = mask + (size_t)tk[r] * QT;
            for (int k = lane; k < QT; k += 32) mrow[k] = 1.0f;
        }
        return;
    }

    const int pq = qidx - 1;
    const int qr = (pq * 2731) >> 16;          // exact /24 for pq<576
    const int qc = pq - 24 * qr;

    const int off = (bh0 + qidx) & 1;          // tok parity (same all rows)
    const float2* up[4];
    float2*       mp[4];
#pragma unroll
    for (int r = 0; r < 4; r++) {
        const size_t base = (size_t)tk[r] * QT + off;
        up[r] = (const float2*)(u + base);
        mp[r] = (float2*)(mask + base);
    }
    if (off == 1 && lane == 0) {
#pragma unroll
        for (int r = 0; r < 4; r++)
            mask[(size_t)tk[r] * QT] = 1.0f;   // CLS key column: mask==1
    }

    // Walker at pair's first element: pk0 = off + 2*lane - 1.
    // off==0, lane==0 -> virtual pk=-1 (k=0 is CLS, geometry overridden).
    int r0, cc;
    {
        const int pk0 = off + 2 * lane - 1;
        if (pk0 < 0) { r0 = 0; cc = -1; }
        else { r0 = (pk0 * 2731) >> 16; cc = pk0 - 24 * r0; }
    }
    float fdy = (float)(qr - r0);
    float fdx = (float)(qc - cc);
    const bool iscls = (off == 0) && (lane == 0);

    // prefetch iteration 0
    float2 cu[4];
#pragma unroll
    for (int r = 0; r < 4; r++) cu[r] = __ldg(up[r] + lane);

#pragma unroll 1
    for (int it = 0; it < 9; it++) {
        float2 nu[4];
        if (it < 8) {
#pragma unroll
            for (int r = 0; r < 4; r++)
                nu[r] = __ldg(up[r] + lane + 32 * (it + 1));
        }

        // shared geometry for this pair
        float dy1 = fdy, dx1 = fdx;
        if (it == 0 && iscls) { dy1 = 0.0f; dx1 = 0.0f; }
        const bool  wrap = (cc == 23);
        const float dy2  = wrap ? fdy - 1.0f  : fdy;
        const float dx2  = wrap ? fdx + 23.0f : fdx - 1.0f;
        const float A1 = dy1 * dy1, B1 = dy1 * dx1, C1 = dx1 * dx1;
        const float A2 = dy2 * dy2, B2 = dy2 * dx2, C2 = dx2 * dx2;

#pragma unroll
        for (int r = 0; r < 4; r++) {
            float t21 = fmaf(cb[r], B1, fmaf(ca[r], A1, cd[r] * C1));
            float t22 = fmaf(cb[r], B2, fmaf(ca[r], A2, cd[r] * C2));
            t21 = fminf(t21, 0.0f);            // replicate min(probs,1)
            t22 = fminf(t22, 0.0f);
            const float pe1 = exp2f(t21);
            const float pe2 = exp2f(t22);
            const float u1 = cu[r].x, u2 = cu[r].y;

            float m1, m2;
            if (isT1) {
                // m = pu / (1 - u - p + 2pu)
                const float n1 = pe1 * u1, n2 = pe2 * u2;
                float w1 = (1.0f - u1) - pe1;
                float w2 = (1.0f - u2) - pe2;
                const float d1 = fmaf(2.0f, n1, w1);
                const float d2 = fmaf(2.0f, n2, w2);
                m1 = __fdividef(n1, d1);
                m2 = __fdividef(n2, d2);
            } else {
                const float x1 = t21 + __log2f(u1)
                               - __log2f((1.0f - pe1) * (1.0f - u1));
                const float x2 = t22 + __log2f(u2)
                               - __log2f((1.0f - pe2) * (1.0f - u2));
                m1 = __fdividef(1.0f, 1.0f + exp2f(-x1 * invT));
                m2 = __fdividef(1.0f, 1.0f + exp2f(-x2 * invT));
            }
            mp[r][lane + 32 * it] = make_float2(m1, m2);
            cu[r] = nu[r];
        }

        // advance pair start by 64 keys: +2 rows, +16 cols (<=1 wrap)
        cc += 16; fdy -= 2.0f; fdx -= 16.0f;
        if (cc >= 24) { cc -= 24; fdy -= 1.0f; fdx += 24.0f; }
    }

    if (off == 0 && lane == 0) {
        // tail singleton k=576 -> pk=575 -> (r,cc)=(23,23)
        const float dy = (float)(qr - 23);
        const float dx = (float)(qc - 23);
        const float A = dy * dy, B = dy * dx, C = dx * dx;
#pragma unroll
        for (int r = 0; r < 4; r++) {
            float t2 = fmaf(cb[r], B, fmaf(ca[r], A, cd[r] * C));
            t2 = fminf(t2, 0.0f);
            const float pe = exp2f(t2);
            const float uu = __ldg(u + (size_t)tk[r] * QT + 576);
            float m;
            if (isT1) {
                const float n = pe * uu;
                const float w = (1.0f - uu) - pe;
                m = __fdividef(n, fmaf(2.0f, n, w));
            } else {
                const float x2 = t2 + __log2f(uu)
                               - __log2f((1.0f - pe) * (1.0f - uu));
                m = __fdividef(1.0f, 1.0f + exp2f(-x2 * invT));
            }
            mask[(size_t)tk[r] * QT + 576] = m;
        }
    }
}

// ---------------------------------------------------------------------------
extern "C" void kernel_launch(void* const* d_in, const int* in_sizes, int n_in,
                              void* d_out, int out_size)
{
    const float* query = (const float*)d_in[0];
    const float* W1    = (const float*)d_in[1];
    const float* b1    = (const float*)d_in[2];
    const float* W2    = (const float*)d_in[3];
    const float* b2    = (const float*)d_in[4];
    // d_in[5] = dists (computed analytically in-kernel)
    const float* u     = (const float*)d_in[6];
    const float* temp  = (const float*)d_in[7];

    float* mask = (float*)d_out;

    float* sigma;
    if (out_size >= MASK_ELEMS + SIGMA_ELEMS) {
        sigma = (float*)d_out + MASK_ELEMS;
    } else {
        cudaGetSymbolAddress((void**)&sigma, g_sigma_fallback);
    }

    mgk_fused<<<NTOK / 32, 256>>>(query, W1, b1, W2, b2, u, temp, mask, sigma);
}

// round 11
// speedup vs baseline: 1.0266x; 1.0266x over previous
#include <cuda_runtime.h>
#include <cuda_bf16.h>

#define QT     577
#define NTOK   55392                  // 96 * 577 rows
#define MASK_ELEMS (96 * 577 * 577)
#define SIGMA_ELEMS (NTOK * 4)
#define ROWSTRIDE 7990296             // 24*577*577: element stride between
                                      // the warp's consecutive bh rows
// Fallback Sigma target if out buffer doesn't include Sigma
__device__ float g_sigma_fallback[SIGMA_ELEMS];

// ---------------------------------------------------------------------------
// Fused kernel: ONE WARP = ONE qidx x FOUR bh ROWS, bh = g + 24r so the
// row-to-row element stride is the compile-time constant ROWSTRIDE (keeps
// parity identical AND removes per-row pointer arrays -> low reg pressure,
// 5 blocks/SM). Geometry (walker + wrap + A,B,C products) computed once per
// float2 pair and reused by all 4 rows; -0.5*log2(e) pre-folded into the
// inverse-covariance coefficients (fmax(quad,0) -> fmin(t2,0)).
// T==1 closed form: m = pu / (1 - u - p + 2pu).
// max_k kernel == 1 exactly (PD form, zero CLS/self distance) => no row
// reduction needed.
// ---------------------------------------------------------------------------
__global__ __launch_bounds__(256, 5)
void mgk_fused(const float* __restrict__ q,
               const float* __restrict__ W1, const float* __restrict__ b1,
               const float* __restrict__ W2, const float* __restrict__ b2,
               const float* __restrict__ u,  const float* __restrict__ temp,
               float* __restrict__ mask, float* __restrict__ sigma)
{
    __shared__ float w1t[64 * 68];    // W1 transposed: w1t[j*68+k] = W1[k][j]
    __shared__ float qs[8][4][68];    // per-warp 4 q rows (float4-aligned)

    const int tid  = threadIdx.x;
    const int wid  = tid >> 5;
    const int lane = tid & 31;

    // ---- stage W1 transposed (once per block) ----
    for (int i = tid; i < 4096; i += 256) {
        const int k = i >> 6, j = i & 63;
        w1t[j * 68 + k] = W1[i];
    }

    const int j0 = lane, j1 = lane + 32;
    const float bb0 = b1[j0], bb1 = b1[j1];
    const float w2a0 = W2[j0 * 3 + 0], w2b0 = W2[j0 * 3 + 1], w2c0 = W2[j0 * 3 + 2];
    const float w2a1 = W2[j1 * 3 + 0], w2b1 = W2[j1 * 3 + 1], w2c1 = W2[j1 * 3 + 2];
    const float b20 = b2[0], b21 = b2[1], b22 = b2[2];
    const float T    = temp[0];
    const bool  isT1 = (T == 1.0f);
    const float invT = 1.0f / T;

    // ---- warp -> (qidx, 4 bh rows g, g+24, g+48, g+72) ----
    const int wg   = blockIdx.x * 8 + wid;     // 0..13847
    const int qidx = wg % 577;
    const int g    = wg / 577;                 // 0..23
    const int tok0 = g * QT + qidx;            // row r: tok0 + r*24*577

    // ---- stage the warp's 4 q rows ----
#pragma unroll
    for (int r = 0; r < 4; r++) {
        const size_t qb = (size_t)(tok0 + r * (24 * QT)) * 64;
        qs[wid][r][lane]      = q[qb + lane];
        qs[wid][r][lane + 32] = q[qb + 32 + lane];
    }
    __syncthreads();

    // ---- layer 1: 4 rows x 2 units; w-loads amortized across rows ----
    float a00r = bb0, a01r = bb0, a02r = bb0, a03r = bb0;
    float a10r = bb1, a11r = bb1, a12r = bb1, a13r = bb1;
#pragma unroll
    for (int kk = 0; kk < 16; kk++) {
        const float4 wa = *(const float4*)&w1t[j0 * 68 + 4 * kk];
        const float4 wb = *(const float4*)&w1t[j1 * 68 + 4 * kk];
        const float4 q0 = *(const float4*)&qs[wid][0][4 * kk];
        const float4 q1 = *(const float4*)&qs[wid][1][4 * kk];
        const float4 q2 = *(const float4*)&qs[wid][2][4 * kk];
        const float4 q3 = *(const float4*)&qs[wid][3][4 * kk];
        a00r = fmaf(q0.x, wa.x, a00r); a00r = fmaf(q0.y, wa.y, a00r);
        a00r = fmaf(q0.z, wa.z, a00r); a00r = fmaf(q0.w, wa.w, a00r);
        a01r = fmaf(q1.x, wa.x, a01r); a01r = fmaf(q1.y, wa.y, a01r);
        a01r = fmaf(q1.z, wa.z, a01r); a01r = fmaf(q1.w, wa.w, a01r);
        a02r = fmaf(q2.x, wa.x, a02r); a02r = fmaf(q2.y, wa.y, a02r);
        a02r = fmaf(q2.z, wa.z, a02r); a02r = fmaf(q2.w, wa.w, a02r);
        a03r = fmaf(q3.x, wa.x, a03r); a03r = fmaf(q3.y, wa.y, a03r);
        a03r = fmaf(q3.z, wa.z, a03r); a03r = fmaf(q3.w, wa.w, a03r);
        a10r = fmaf(q0.x, wb.x, a10r); a10r = fmaf(q0.y, wb.y, a10r);
        a10r = fmaf(q0.z, wb.z, a10r); a10r = fmaf(q0.w, wb.w, a10r);
        a11r = fmaf(q1.x, wb.x, a11r); a11r = fmaf(q1.y, wb.y, a11r);
        a11r = fmaf(q1.z, wb.z, a11r); a11r = fmaf(q1.w, wb.w, a11r);
        a12r = fmaf(q2.x, wb.x, a12r); a12r = fmaf(q2.y, wb.y, a12r);
        a12r = fmaf(q2.z, wb.z, a12r); a12r = fmaf(q2.w, wb.w, a12r);
        a13r = fmaf(q3.x, wb.x, a13r); a13r = fmaf(q3.y, wb.y, a13r);
        a13r = fmaf(q3.z, wb.z, a13r); a13r = fmaf(q3.w, wb.w, a13r);
    }

    // ---- per-row: GELU, reduce, tail -> pre-scaled inverse coefs ----
    const float K2 = -0.72134752044448170f;    // -0.5*log2(e)
    float ca[4], cb[4], cd[4];
#pragma unroll
    for (int r4 = 0; r4 < 4; r4++) {
        const float h0 = (r4 == 0) ? a00r : (r4 == 1) ? a01r
                        : (r4 == 2) ? a02r : a03r;
        const float h1 = (r4 == 0) ? a10r : (r4 == 1) ? a11r
                        : (r4 == 2) ? a12r : a13r;

        // Exact GELU (erf-based, matches approximate=False)
        const float g0 = 0.5f * h0 * (1.0f + erff(h0 * 0.70710678118654752f));
        const float g1 = 0.5f * h1 * (1.0f + erff(h1 * 0.70710678118654752f));

        float p0 = fmaf(g1, w2a1, g0 * w2a0);
        float p1 = fmaf(g1, w2b1, g0 * w2b0);
        float p2 = fmaf(g1, w2c1, g0 * w2c0);
#pragma unroll
        for (int off = 16; off > 0; off >>= 1) {
            p0 += __shfl_xor_sync(0xffffffffu, p0, off);
            p1 += __shfl_xor_sync(0xffffffffu, p1, off);
            p2 += __shfl_xor_sync(0xffffffffu, p2, off);
        }

        const float s0 = p0 + b20, s1 = p1 + b21, s2 = p2 + b22;
        const float sy  = expf(s0) + 1.0f;
        const float sx  = expf(s1) + 1.0f;
        const float rho = tanhf(s2) * 0.99f;
        const float cov = sy * sx * rho;
        if (lane == 0)
            ((float4*)sigma)[tok0 + r4 * (24 * QT)] =
                make_float4(sy * sy, cov, cov, sx * sx);

        const float om = 1.0f - rho * rho;
        ca[r4] = K2 / (sy * sy * om);                 // scaled c00
        cb[r4] = K2 * (-2.0f * rho) / (sy * sx * om); // scaled 2*c01
        cd[r4] = K2 / (sx * sx * om);                 // scaled c11
    }

    // ---- mask rows ----
    const unsigned base0 = (unsigned)tok0 * QT;       // row-0 element index

    if (qidx == 0) {
        // CLS query rows: probs=1 -> mask=1 for ANY T.
#pragma unroll
        for (int r = 0; r < 4; r++) {
            float* mrow = mask + base0 + (unsigned)r * ROWSTRIDE;
            for (int k = lane; k < QT; k += 32) mrow[k] = 1.0f;
        }
        return;
    }

    const int pq = qidx - 1;
    const int qr = (pq * 2731) >> 16;          // exact /24 for pq<576
    const int qc = pq - 24 * qr;

    const int off = (g + qidx) & 1;            // tok parity (same all rows)
    if (off == 1 && lane == 0) {
#pragma unroll
        for (int r = 0; r < 4; r++)
            mask[base0 + (unsigned)r * ROWSTRIDE] = 1.0f;  // CLS key column
    }

    // float2-unit index of this lane's first pair (global idx even)
    unsigned ui = (base0 + (unsigned)off) >> 1;
    ui += (unsigned)lane;
    const float2* u2 = (const float2*)u;
    float2*       m2 = (float2*)mask;

    // Walker at pair's first element: pk0 = off + 2*lane - 1.
    // off==0, lane==0 -> virtual pk=-1 (k=0 is CLS, geometry overridden).
    int r0, cc;
    {
        const int pk0 = off + 2 * lane - 1;
        if (pk0 < 0) { r0 = 0; cc = -1; }
        else { r0 = (pk0 * 2731) >> 16; cc = pk0 - 24 * r0; }
    }
    float fdy = (float)(qr - r0);
    float fdx = (float)(qc - cc);
    const bool iscls = (off == 0) && (lane == 0);

#pragma unroll 1
    for (int it = 0; it < 9; it++) {
        // batch this iteration's 4 row loads (constant index offsets)
        float2 uu0 = __ldg(u2 + ui);
        float2 uu1 = __ldg(u2 + ui + (ROWSTRIDE / 2));
        float2 uu2 = __ldg(u2 + ui + 2 * (ROWSTRIDE / 2));
        float2 uu3 = __ldg(u2 + ui + 3 * (ROWSTRIDE / 2));

        // shared geometry for this pair
        float dy1 = fdy, dx1 = fdx;
        if (it == 0 && iscls) { dy1 = 0.0f; dx1 = 0.0f; }
        const bool  wrap = (cc == 23);
        const float dy2  = wrap ? fdy - 1.0f  : fdy;
        const float dx2  = wrap ? fdx + 23.0f : fdx - 1.0f;
        const float A1 = dy1 * dy1, B1 = dy1 * dx1, C1 = dx1 * dx1;
        const float A2 = dy2 * dy2, B2 = dy2 * dx2, C2 = dx2 * dx2;

#pragma unroll
        for (int r = 0; r < 4; r++) {
            const float2 cu = (r == 0) ? uu0 : (r == 1) ? uu1
                             : (r == 2) ? uu2 : uu3;
            float t21 = fmaf(cb[r], B1, fmaf(ca[r], A1, cd[r] * C1));
            float t22 = fmaf(cb[r], B2, fmaf(ca[r], A2, cd[r] * C2));
            t21 = fminf(t21, 0.0f);            // replicate min(probs,1)
            t22 = fminf(t22, 0.0f);
            const float pe1 = exp2f(t21);
            const float pe2 = exp2f(t22);
            const float u1 = cu.x, u2v = cu.y;

            float m1, mm2;
            if (isT1) {
                // m = pu / (1 - u - p + 2pu)
                const float n1 = pe1 * u1, n2 = pe2 * u2v;
                const float w1 = (1.0f - u1)  - pe1;
                const float w2 = (1.0f - u2v) - pe2;
                m1  = __fdividef(n1, fmaf(2.0f, n1, w1));
                mm2 = __fdividef(n2, fmaf(2.0f, n2, w2));
            } else {
                const float x1 = t21 + __log2f(u1)
                               - __log2f((1.0f - pe1) * (1.0f - u1));
                const float x2 = t22 + __log2f(u2v)
                               - __log2f((1.0f - pe2) * (1.0f - u2v));
                m1  = __fdividef(1.0f, 1.0f + exp2f(-x1 * invT));
                mm2 = __fdividef(1.0f, 1.0f + exp2f(-x2 * invT));
            }
            m2[ui + (unsigned)r * (ROWSTRIDE / 2)] = make_float2(m1, mm2);
        }

        // advance pair start by 64 keys: +2 rows, +16 cols (<=1 wrap)
        ui += 32;
        cc += 16; fdy -= 2.0f; fdx -= 16.0f;
        if (cc >= 24) { cc -= 24; fdy -= 1.0f; fdx += 24.0f; }
    }

    if (off == 0 && lane == 0) {
        // tail singleton k=576 -> pk=575 -> (r,cc)=(23,23)
        const float dy = (float)(qr - 23);
        const float dx = (float)(qc - 23);
        const float A = dy * dy, B = dy * dx, C = dx * dx;
#pragma unroll
        for (int r = 0; r < 4; r++) {
            float t2 = fmaf(cb[r], B, fmaf(ca[r], A, cd[r] * C));
            t2 = fminf(t2, 0.0f);
            const float pe = exp2f(t2);
            const unsigned ei = base0 + (unsigned)r * ROWSTRIDE + 576;
            const float uu = __ldg(u + ei);
            float m;
            if (isT1) {
                const float n = pe * uu;
                const float w = (1.0f - uu) - pe;
                m = __fdividef(n, fmaf(2.0f, n, w));
            } else {
                const float x2 = t2 + __log2f(uu)
                               - __log2f((1.0f - pe) * (1.0f - uu));
                m = __fdividef(1.0f, 1.0f + exp2f(-x2 * invT));
            }
            mask[ei] = m;
        }
    }
}

// ---------------------------------------------------------------------------
extern "C" void kernel_launch(void* const* d_in, const int* in_sizes, int n_in,
                              void* d_out, int out_size)
{
    const float* query = (const float*)d_in[0];
    const float* W1    = (const float*)d_in[1];
    const float* b1    = (const float*)d_in[2];
    const float* W2    = (const float*)d_in[3];
    const float* b2    = (const float*)d_in[4];
    // d_in[5] = dists (computed analytically in-kernel)
    const float* u     = (const float*)d_in[6];
    const float* temp  = (const float*)d_in[7];

    float* mask = (float*)d_out;

    float* sigma;
    if (out_size >= MASK_ELEMS + SIGMA_ELEMS) {
        sigma = (float*)d_out + MASK_ELEMS;
    } else {
        cudaGetSymbolAddress((void**)&sigma, g_sigma_fallback);
    }

    mgk_fused<<<NTOK / 32, 256>>>(query, W1, b1, W2, b2, u, temp, mask, sigma);
}

// round 12
// speedup vs baseline: 1.1587x; 1.1287x over previous
#include <cuda_runtime.h>
#include <cuda_bf16.h>

#define QT     577
#define NTOK   55392                  // 96 * 577 rows
#define MASK_ELEMS (96 * 577 * 577)
#define SIGMA_ELEMS (NTOK * 4)
#define ROWSTRIDE 7990296             // 24*577*577 elements between warp rows
#define RS2 (ROWSTRIDE / 2)           // in float2 units

// Fallback Sigma target if out buffer doesn't include Sigma
__device__ float g_sigma_fallback[SIGMA_ELEMS];

// ---------------------------------------------------------------------------
// Fused kernel: ONE WARP = ONE qidx x FOUR bh ROWS (bh = g + 24r, constant
// element stride ROWSTRIDE, shared parity and shared (dy,dx) geometry).
// Mask phase runs as TWO PASSES of 2 rows; each pass issues ALL 18 LDG.64
// (9 iterations x 2 rows) back-to-back before any consumer -> ~18 loads in
// flight per warp (vs 4), breaking the latency equilibrium seen in r9-r11.
// Geometry walker is computed once per pair-iteration and shared by the 2
// rows; -0.5*log2(e) pre-folded into coefficients (fmax(quad,0)->fmin(t2,0)).
// T==1 closed form: m = pu / (1 - u - p + 2pu).
// max_k kernel == 1 exactly (PD form, zero CLS/self distance).
// ---------------------------------------------------------------------------
__global__ __launch_bounds__(256, 4)
void mgk_fused(const float* __restrict__ q,
               const float* __restrict__ W1, const float* __restrict__ b1,
               const float* __restrict__ W2, const float* __restrict__ b2,
               const float* __restrict__ u,  const float* __restrict__ temp,
               float* __restrict__ mask, float* __restrict__ sigma)
{
    __shared__ float w1t[64 * 68];    // W1 transposed: w1t[j*68+k] = W1[k][j]
    __shared__ float qs[8][4][68];    // per-warp 4 q rows (float4-aligned)

    const int tid  = threadIdx.x;
    const int wid  = tid >> 5;
    const int lane = tid & 31;

    // ---- stage W1 transposed (once per block) ----
    for (int i = tid; i < 4096; i += 256) {
        const int k = i >> 6, j = i & 63;
        w1t[j * 68 + k] = W1[i];
    }

    const int j0 = lane, j1 = lane + 32;
    const float bb0 = b1[j0], bb1 = b1[j1];
    const float w2a0 = W2[j0 * 3 + 0], w2b0 = W2[j0 * 3 + 1], w2c0 = W2[j0 * 3 + 2];
    const float w2a1 = W2[j1 * 3 + 0], w2b1 = W2[j1 * 3 + 1], w2c1 = W2[j1 * 3 + 2];
    const float b20 = b2[0], b21 = b2[1], b22 = b2[2];
    const float T    = temp[0];
    const bool  isT1 = (T == 1.0f);
    const float invT = 1.0f / T;

    // ---- warp -> (qidx, 4 bh rows g, g+24, g+48, g+72) ----
    const int wg   = blockIdx.x * 8 + wid;     // 0..13847
    const int qidx = wg % 577;
    const int g    = wg / 577;                 // 0..23
    const int tok0 = g * QT + qidx;            // row r: tok0 + r*24*577

    // ---- stage the warp's 4 q rows ----
#pragma unroll
    for (int r = 0; r < 4; r++) {
        const size_t qb = (size_t)(tok0 + r * (24 * QT)) * 64;
        qs[wid][r][lane]      = q[qb + lane];
        qs[wid][r][lane + 32] = q[qb + 32 + lane];
    }
    __syncthreads();

    // ---- layer 1: 4 rows x 2 units; w-loads amortized across rows ----
    float a00r = bb0, a01r = bb0, a02r = bb0, a03r = bb0;
    float a10r = bb1, a11r = bb1, a12r = bb1, a13r = bb1;
#pragma unroll
    for (int kk = 0; kk < 16; kk++) {
        const float4 wa = *(const float4*)&w1t[j0 * 68 + 4 * kk];
        const float4 wb = *(const float4*)&w1t[j1 * 68 + 4 * kk];
        const float4 q0 = *(const float4*)&qs[wid][0][4 * kk];
        const float4 q1 = *(const float4*)&qs[wid][1][4 * kk];
        const float4 q2 = *(const float4*)&qs[wid][2][4 * kk];
        const float4 q3 = *(const float4*)&qs[wid][3][4 * kk];
        a00r = fmaf(q0.x, wa.x, a00r); a00r = fmaf(q0.y, wa.y, a00r);
        a00r = fmaf(q0.z, wa.z, a00r); a00r = fmaf(q0.w, wa.w, a00r);
        a01r = fmaf(q1.x, wa.x, a01r); a01r = fmaf(q1.y, wa.y, a01r);
        a01r = fmaf(q1.z, wa.z, a01r); a01r = fmaf(q1.w, wa.w, a01r);
        a02r = fmaf(q2.x, wa.x, a02r); a02r = fmaf(q2.y, wa.y, a02r);
        a02r = fmaf(q2.z, wa.z, a02r); a02r = fmaf(q2.w, wa.w, a02r);
        a03r = fmaf(q3.x, wa.x, a03r); a03r = fmaf(q3.y, wa.y, a03r);
        a03r = fmaf(q3.z, wa.z, a03r); a03r = fmaf(q3.w, wa.w, a03r);
        a10r = fmaf(q0.x, wb.x, a10r); a10r = fmaf(q0.y, wb.y, a10r);
        a10r = fmaf(q0.z, wb.z, a10r); a10r = fmaf(q0.w, wb.w, a10r);
        a11r = fmaf(q1.x, wb.x, a11r); a11r = fmaf(q1.y, wb.y, a11r);
        a11r = fmaf(q1.z, wb.z, a11r); a11r = fmaf(q1.w, wb.w, a11r);
        a12r = fmaf(q2.x, wb.x, a12r); a12r = fmaf(q2.y, wb.y, a12r);
        a12r = fmaf(q2.z, wb.z, a12r); a12r = fmaf(q2.w, wb.w, a12r);
        a13r = fmaf(q3.x, wb.x, a13r); a13r = fmaf(q3.y, wb.y, a13r);
        a13r = fmaf(q3.z, wb.z, a13r); a13r = fmaf(q3.w, wb.w, a13r);
    }

    const float K2 = -0.72134752044448170f;    // -0.5*log2(e)
    const unsigned base0 = (unsigned)tok0 * QT;

    // geometry of the query patch (shared by all 4 rows)
    const int pq = qidx - 1;                   // valid when qidx>0
    const int qr = (pq * 2731) >> 16;          // exact /24 for 0<=pq<576
    const int qc = pq - 24 * qr;

    const int off = (g + qidx) & 1;            // tok parity (same all rows)
    if (qidx != 0 && off == 1 && lane == 0) {
#pragma unroll
        for (int r = 0; r < 4; r++)
            mask[base0 + (unsigned)r * ROWSTRIDE] = 1.0f;  // CLS key column
    }

    // saved walker init: pair's first element pk0 = off + 2*lane - 1
    // (off==0, lane==0 -> virtual pk=-1; k=0 is CLS, geometry overridden)
    int r0i, cci;
    {
        const int pk0 = off + 2 * lane - 1;
        if (pk0 < 0) { r0i = 0; cci = -1; }
        else { r0i = (pk0 * 2731) >> 16; cci = pk0 - 24 * r0i; }
    }
    const float fdyi = (float)(qr - r0i);
    const float fdxi = (float)(qc - cci);
    const bool  iscls = (off == 0) && (lane == 0);

    const unsigned ui0 = ((base0 + (unsigned)off) >> 1) + (unsigned)lane;
    const float2* u2v = (const float2*)u;
    float2*       m2v = (float2*)mask;

    // ---- two passes of 2 rows ----
#pragma unroll
    for (int pass = 0; pass < 2; pass++) {
        const int rA = 2 * pass, rB = 2 * pass + 1;

        // -- finalize MLP for the pass's 2 rows --
        float caA, cbA, cdA, caB, cbB, cdB;
#pragma unroll
        for (int rr = 0; rr < 2; rr++) {
            const int r4 = 2 * pass + rr;
            const float h0 = (r4 == 0) ? a00r : (r4 == 1) ? a01r
                            : (r4 == 2) ? a02r : a03r;
            const float h1 = (r4 == 0) ? a10r : (r4 == 1) ? a11r
                            : (r4 == 2) ? a12r : a13r;

            // Exact GELU (erf-based, matches approximate=False)
            const float g0 = 0.5f * h0 * (1.0f + erff(h0 * 0.70710678118654752f));
            const float g1 = 0.5f * h1 * (1.0f + erff(h1 * 0.70710678118654752f));

            float p0 = fmaf(g1, w2a1, g0 * w2a0);
            float p1 = fmaf(g1, w2b1, g0 * w2b0);
            float p2 = fmaf(g1, w2c1, g0 * w2c0);
#pragma unroll
            for (int o = 16; o > 0; o >>= 1) {
                p0 += __shfl_xor_sync(0xffffffffu, p0, o);
                p1 += __shfl_xor_sync(0xffffffffu, p1, o);
                p2 += __shfl_xor_sync(0xffffffffu, p2, o);
            }
            const float s0 = p0 + b20, s1 = p1 + b21, s2 = p2 + b22;
            const float sy  = expf(s0) + 1.0f;
            const float sx  = expf(s1) + 1.0f;
            const float rho = tanhf(s2) * 0.99f;
            const float cov = sy * sx * rho;
            if (lane == 0)
                ((float4*)sigma)[tok0 + r4 * (24 * QT)] =
                    make_float4(sy * sy, cov, cov, sx * sx);

            const float om = 1.0f - rho * rho;
            const float ca = K2 / (sy * sy * om);
            const float cb = K2 * (-2.0f * rho) / (sy * sx * om);
            const float cd = K2 / (sx * sx * om);
            if (rr == 0) { caA = ca; cbA = cb; cdA = cd; }
            else         { caB = ca; cbB = cb; cdB = cd; }
        }

        if (qidx == 0) {
            // CLS query rows: probs=1 -> mask=1 for ANY T.
#pragma unroll
            for (int rr = 0; rr < 2; rr++) {
                float* mrow = mask + base0 + (unsigned)(2 * pass + rr) * ROWSTRIDE;
                for (int k = lane; k < QT; k += 32) mrow[k] = 1.0f;
            }
            continue;
        }

        // -- batch ALL 18 loads for this pass (9 iterations x 2 rows) --
        const unsigned uiA = ui0 + (unsigned)rA * RS2;
        const unsigned uiB = ui0 + (unsigned)rB * RS2;
        float2 uA[9], uB[9];
#pragma unroll
        for (int it = 0; it < 9; it++) uA[it] = __ldg(u2v + uiA + 32u * it);
#pragma unroll
        for (int it = 0; it < 9; it++) uB[it] = __ldg(u2v + uiB + 32u * it);

        // -- walker replay + compute --
        int   cc  = cci;
        float fdy = fdyi, fdx = fdxi;
#pragma unroll
        for (int it = 0; it < 9; it++) {
            float dy1 = fdy, dx1 = fdx;
            if (it == 0 && iscls) { dy1 = 0.0f; dx1 = 0.0f; }
            const bool  wrap = (cc == 23);
            const float dy2  = wrap ? fdy - 1.0f  : fdy;
            const float dx2  = wrap ? fdx + 23.0f : fdx - 1.0f;
            const float A1 = dy1 * dy1, B1 = dy1 * dx1, C1 = dx1 * dx1;
            const float A2 = dy2 * dy2, B2 = dy2 * dx2, C2 = dx2 * dx2;

#pragma unroll
            for (int rr = 0; rr < 2; rr++) {
                const float ca = rr ? caB : caA;
                const float cb = rr ? cbB : cbA;
                const float cd = rr ? cdB : cdA;
                const float2 cu = rr ? uB[it] : uA[it];

                float t21 = fmaf(cb, B1, fmaf(ca, A1, cd * C1));
                float t22 = fmaf(cb, B2, fmaf(ca, A2, cd * C2));
                t21 = fminf(t21, 0.0f);        // replicate min(probs,1)
                t22 = fminf(t22, 0.0f);
                const float pe1 = exp2f(t21);
                const float pe2 = exp2f(t22);
                const float u1 = cu.x, uu2 = cu.y;

                float m1, mm2;
                if (isT1) {
                    // m = pu / (1 - u - p + 2pu)
                    const float n1 = pe1 * u1, n2 = pe2 * uu2;
                    const float w1 = (1.0f - u1)  - pe1;
                    const float w2 = (1.0f - uu2) - pe2;
                    m1  = __fdividef(n1, fmaf(2.0f, n1, w1));
                    mm2 = __fdividef(n2, fmaf(2.0f, n2, w2));
                } else {
                    const float x1 = t21 + __log2f(u1)
                                   - __log2f((1.0f - pe1) * (1.0f - u1));
                    const float x2 = t22 + __log2f(uu2)
                                   - __log2f((1.0f - pe2) * (1.0f - uu2));
                    m1  = __fdividef(1.0f, 1.0f + exp2f(-x1 * invT));
                    mm2 = __fdividef(1.0f, 1.0f + exp2f(-x2 * invT));
                }
                m2v[(rr ? uiB : uiA) + 32u * it] = make_float2(m1, mm2);
            }

            // advance pair start by 64 keys: +2 rows, +16 cols (<=1 wrap)
            cc += 16; fdy -= 2.0f; fdx -= 16.0f;
            if (cc >= 24) { cc -= 24; fdy -= 1.0f; fdx += 24.0f; }
        }

        // -- tail singleton k=576 (only when off==0): pk=575 -> (23,23) --
        if (off == 0 && lane == 0) {
            const float dy = (float)(qr - 23);
            const float dx = (float)(qc - 23);
            const float A = dy * dy, B = dy * dx, C = dx * dx;
#pragma unroll
            for (int rr = 0; rr < 2; rr++) {
                const float ca = rr ? caB : caA;
                const float cb = rr ? cbB : cbA;
                const float cd = rr ? cdB : cdA;
                float t2 = fmaf(cb, B, fmaf(ca, A, cd * C));
                t2 = fminf(t2, 0.0f);
                const float pe = exp2f(t2);
                const unsigned ei = base0
                    + (unsigned)(2 * pass + rr) * ROWSTRIDE + 576u;
                const float uu = __ldg(u + ei);
                float m;
                if (isT1) {
                    const float n = pe * uu;
                    const float w = (1.0f - uu) - pe;
                    m = __fdividef(n, fmaf(2.0f, n, w));
                } else {
                    const float x2 = t2 + __log2f(uu)
                                   - __log2f((1.0f - pe) * (1.0f - uu));
                    m = __fdividef(1.0f, 1.0f + exp2f(-x2 * invT));
                }
                mask[ei] = m;
            }
        }
    }
}

// ---------------------------------------------------------------------------
extern "C" void kernel_launch(void* const* d_in, const int* in_sizes, int n_in,
                              void* d_out, int out_size)
{
    const float* query = (const float*)d_in[0];
    const float* W1    = (const float*)d_in[1];
    const float* b1    = (const float*)d_in[2];
    const float* W2    = (const float*)d_in[3];
    const float* b2    = (const float*)d_in[4];
    // d_in[5] = dists (computed analytically in-kernel)
    const float* u     = (const float*)d_in[6];
    const float* temp  = (const float*)d_in[7];

    float* mask = (float*)d_out;

    float* sigma;
    if (out_size >= MASK_ELEMS + SIGMA_ELEMS) {
        sigma = (float*)d_out + MASK_ELEMS;
    } else {
        cudaGetSymbolAddress((void**)&sigma, g_sigma_fallback);
    }

    mgk_fused<<<NTOK / 32, 256>>>(query, W1, b1, W2, b2, u, temp, mask, sigma);
}